// round 15
// baseline (speedup 1.0000x reference)
#include <cuda_runtime.h>
#include <cuda_bf16.h>
#include <math.h>

// Problem shape
#define Bsz 4
#define Ssz 2048
#define Hsz 2048
#define NH  16
#define HD  128
#define Msz (Bsz*Ssz)          // 8192
#define MK  ((size_t)Msz*Hsz)  // 16,777,216
#define WK  ((size_t)Hsz*Hsz)  // 4,194,304

// 1/sqrt(128) * log2(e)  (attention uses exp2; scale folded into Q)
#define QSCALE 0.12751949974651278f

// ---------------- scratch (__device__ globals; no cudaMalloc allowed) ------
__device__ __nv_bfloat16 g_xhi[MK], g_xlo[MK];
__device__ __nv_bfloat16 g_whi[4][WK], g_wlo[4][WK];   // W^T split, [N][K]
__device__ __nv_bfloat16 g_qh[MK], g_ql[MK];           // [B*nh][S][hd], scale folded
__device__ __nv_bfloat16 g_kh[MK], g_kl[MK];           // [B*nh][S][hd]
__device__ __nv_bfloat16 g_vth[MK], g_vtl[MK];         // V^T: [B*nh][hd][S]
__device__ __nv_bfloat16 g_aoh[MK], g_aol[MK];         // [B,S,H] split

// ---------------- PTX helpers ---------------------------------------------
__device__ __forceinline__ unsigned smem_u32(const void* p) {
    unsigned a;
    asm("{ .reg .u64 t; cvta.to.shared.u64 t, %1; cvt.u32.u64 %0, t; }"
        : "=r"(a) : "l"(p));
    return a;
}
__device__ __forceinline__ void ldsm_x4(unsigned& r0, unsigned& r1,
                                        unsigned& r2, unsigned& r3, unsigned a) {
    asm volatile("ldmatrix.sync.aligned.m8n8.x4.shared.b16 {%0,%1,%2,%3}, [%4];"
                 : "=r"(r0), "=r"(r1), "=r"(r2), "=r"(r3) : "r"(a));
}
__device__ __forceinline__ void mma16816(float* c, unsigned a0, unsigned a1,
                                         unsigned a2, unsigned a3,
                                         unsigned b0, unsigned b1) {
    asm volatile(
        "mma.sync.aligned.m16n8k16.row.col.f32.bf16.bf16.f32 "
        "{%0,%1,%2,%3}, {%4,%5,%6,%7}, {%8,%9}, {%0,%1,%2,%3};"
        : "+f"(c[0]), "+f"(c[1]), "+f"(c[2]), "+f"(c[3])
        : "r"(a0), "r"(a1), "r"(a2), "r"(a3), "r"(b0), "r"(b1));
}
__device__ __forceinline__ void cp16(unsigned dst, const void* src) {
    asm volatile("{ .reg .u64 g; cvta.to.global.u64 g, %1;\n\t"
                 "cp.async.cg.shared.global [%0], [g], 16; }"
                 :: "r"(dst), "l"(src) : "memory");
}
#define CP_COMMIT() asm volatile("cp.async.commit_group;" ::: "memory")
#define CP_WAIT1()  asm volatile("cp.async.wait_group 1;" ::: "memory")
#define CP_WAIT0()  asm volatile("cp.async.wait_group 0;" ::: "memory")

// truncating split: hi = top 16 bits (PRMT), lo = rounded exact residual.
__device__ __forceinline__ void split2_trunc(float v0, float v1, unsigned& hi, unsigned& lo) {
    unsigned u0 = __float_as_uint(v0), u1 = __float_as_uint(v1);
    hi = __byte_perm(u0, u1, 0x7632);
    float r0 = v0 - __uint_as_float(u0 & 0xffff0000u);
    float r1 = v1 - __uint_as_float(u1 & 0xffff0000u);
    __nv_bfloat162 l = __float22bfloat162_rn(make_float2(r0, r1));
    lo = *(unsigned*)&l;
}

// ---------------- conversion kernels --------------------------------------
__global__ void split_kernel(const float* __restrict__ in,
                             __nv_bfloat16* __restrict__ hi,
                             __nv_bfloat16* __restrict__ lo, size_t n) {
    for (size_t i = blockIdx.x * blockDim.x + threadIdx.x; i < n;
         i += (size_t)gridDim.x * blockDim.x) {
        float f = in[i];
        __nv_bfloat16 h = __float2bfloat16(f);
        hi[i] = h;
        lo[i] = __float2bfloat16(f - __bfloat162float(h));
    }
}

// All 4 weight transposes in one launch: W[K][N] -> Wt_hi/lo[N][K], z selects W
__global__ void tsplit4_kernel(const float* __restrict__ W0, const float* __restrict__ W1,
                               const float* __restrict__ W2, const float* __restrict__ W3,
                               __nv_bfloat16* __restrict__ hib,
                               __nv_bfloat16* __restrict__ lob) {
    __shared__ float tile[32][33];
    const float* W = (blockIdx.z == 0) ? W0 : (blockIdx.z == 1) ? W1
                     : (blockIdx.z == 2) ? W2 : W3;
    __nv_bfloat16* hi = hib + (size_t)blockIdx.z * WK;
    __nv_bfloat16* lo = lob + (size_t)blockIdx.z * WK;
    int bx = blockIdx.x * 32, by = blockIdx.y * 32;
    int tx = threadIdx.x, ty = threadIdx.y;
    #pragma unroll
    for (int i = 0; i < 32; i += 8)
        tile[ty + i][tx] = W[(size_t)(by + ty + i) * Hsz + bx + tx];
    __syncthreads();
    #pragma unroll
    for (int i = 0; i < 32; i += 8) {
        int n = bx + ty + i, k = by + tx;
        float f = tile[tx][ty + i];
        __nv_bfloat16 h = __float2bfloat16(f);
        hi[(size_t)n * Hsz + k] = h;
        lo[(size_t)n * Hsz + k] = __float2bfloat16(f - __bfloat162float(h));
    }
}

// ---------------- mma.sync split-bf16 GEMM (256 thr, 2 CTAs/SM) ------------
// Block 128(M)x64(N), K-chunk 64, 8 warps 4(m)x2(n), warp tile 32x32.
#define TPITCH 144
#define A_TILE (128*TPITCH)        // 18432
#define B_TILE (64*TPITCH)         // 9216
#define BUF_B  (2*A_TILE + 2*B_TILE)  // 55296
#define GSMEM  (2*BUF_B)           // 110592

__device__ __forceinline__ void gemm_issue256(
    const __nv_bfloat16* Ah, const __nv_bfloat16* Al,
    const __nv_bfloat16* Bh, const __nv_bfloat16* Bl,
    unsigned sb, int buf, int k0, int tid)
{
    const unsigned base = sb + buf * BUF_B;
    #pragma unroll
    for (int i = 0; i < 4; i++) {
        int idx = tid + i * 256;           // 0..1023
        int row = idx >> 3, ch = idx & 7;
        unsigned off = row * TPITCH + ch * 16;
        const size_t g = (size_t)row * Hsz + k0 + ch * 8;
        cp16(base + off, Ah + g);
        cp16(base + A_TILE + off, Al + g);
    }
    #pragma unroll
    for (int i = 0; i < 2; i++) {
        int idx = tid + i * 256;           // 0..511
        int row = idx >> 3, ch = idx & 7;
        unsigned off = row * TPITCH + ch * 16;
        const size_t g = (size_t)row * Hsz + k0 + ch * 8;
        cp16(base + 2 * A_TILE + off, Bh + g);
        cp16(base + 2 * A_TILE + B_TILE + off, Bl + g);
    }
    CP_COMMIT();
}

// core mainloop: fills acc[2][4][4] for warp tile (wm*32, wn*32)
__device__ __forceinline__ void gemm_core256(
    const __nv_bfloat16* Ah, const __nv_bfloat16* Al,
    const __nv_bfloat16* Bh, const __nv_bfloat16* Bl,
    unsigned sb, int tid, int wm, int wn, int lane, float acc[2][4][4])
{
    const unsigned lm_off = (unsigned)((lane & 15) * TPITCH + (lane >> 4) * 16);

    gemm_issue256(Ah, Al, Bh, Bl, sb, 0, 0, tid);

    #pragma unroll 1
    for (int c = 0; c < 32; c++) {
        const int buf = c & 1;
        if (c < 31) { gemm_issue256(Ah, Al, Bh, Bl, sb, buf ^ 1, (c + 1) * 64, tid); CP_WAIT1(); }
        else        { CP_WAIT0(); }
        __syncthreads();

        const unsigned base   = sb + buf * BUF_B;
        const unsigned a_hi_b = base + (unsigned)(wm * 32 * TPITCH) + lm_off;
        const unsigned a_lo_b = a_hi_b + A_TILE;
        const unsigned b_hi_b = base + 2u * A_TILE + (unsigned)(wn * 32 * TPITCH) + lm_off;
        const unsigned b_lo_b = b_hi_b + B_TILE;

        #pragma unroll
        for (int ks = 0; ks < 4; ks++) {
            const unsigned ko = ks * 32;
            unsigned ah[2][4], al[2][4], bh[2][4], bl[2][4];
            #pragma unroll
            for (int mi = 0; mi < 2; mi++)
                ldsm_x4(ah[mi][0], ah[mi][1], ah[mi][2], ah[mi][3],
                        a_hi_b + mi * 16 * TPITCH + ko);
            #pragma unroll
            for (int bi = 0; bi < 2; bi++)
                ldsm_x4(bh[bi][0], bh[bi][1], bh[bi][2], bh[bi][3],
                        b_hi_b + bi * 16 * TPITCH + ko);
            #pragma unroll
            for (int mi = 0; mi < 2; mi++)
                #pragma unroll
                for (int ni = 0; ni < 4; ni++)
                    mma16816(acc[mi][ni], ah[mi][0], ah[mi][1], ah[mi][2], ah[mi][3],
                             bh[ni >> 1][ni & 1], bh[ni >> 1][(ni & 1) + 2]);
            #pragma unroll
            for (int bi = 0; bi < 2; bi++)
                ldsm_x4(bl[bi][0], bl[bi][1], bl[bi][2], bl[bi][3],
                        b_lo_b + bi * 16 * TPITCH + ko);
            #pragma unroll
            for (int mi = 0; mi < 2; mi++)
                #pragma unroll
                for (int ni = 0; ni < 4; ni++)
                    mma16816(acc[mi][ni], ah[mi][0], ah[mi][1], ah[mi][2], ah[mi][3],
                             bl[ni >> 1][ni & 1], bl[ni >> 1][(ni & 1) + 2]);
            #pragma unroll
            for (int mi = 0; mi < 2; mi++)
                ldsm_x4(al[mi][0], al[mi][1], al[mi][2], al[mi][3],
                        a_lo_b + mi * 16 * TPITCH + ko);
            #pragma unroll
            for (int mi = 0; mi < 2; mi++)
                #pragma unroll
                for (int ni = 0; ni < 4; ni++)
                    mma16816(acc[mi][ni], al[mi][0], al[mi][1], al[mi][2], al[mi][3],
                             bh[ni >> 1][ni & 1], bh[ni >> 1][(ni & 1) + 2]);
        }
        __syncthreads();
    }
}

// Fused Q/K/V projection: blockIdx.z = 0(Q) 1(K) 2(V^T)
__global__ void __launch_bounds__(256, 2) gemm_qkv(
    const __nv_bfloat16* __restrict__ Ahg, const __nv_bfloat16* __restrict__ Alg,
    const __nv_bfloat16* __restrict__ Whi, const __nv_bfloat16* __restrict__ Wlo,
    const float* __restrict__ bq, const float* __restrict__ bk,
    const float* __restrict__ bv,
    __nv_bfloat16* __restrict__ qh, __nv_bfloat16* __restrict__ ql,
    __nv_bfloat16* __restrict__ kh, __nv_bfloat16* __restrict__ kl,
    __nv_bfloat16* __restrict__ vth, __nv_bfloat16* __restrict__ vtl)
{
    extern __shared__ char smc[];
    const unsigned sb = smem_u32(smc);
    const int tid = threadIdx.x, wid = tid >> 5, lane = tid & 31;
    const int wm = wid >> 1, wn = wid & 1;        // 4 x 2 warp grid
    const int z = blockIdx.z;
    const size_t bm = (size_t)blockIdx.y * 128, bn = (size_t)blockIdx.x * 64;

    const __nv_bfloat16* Bh = Whi + (size_t)z * WK + bn * Hsz;
    const __nv_bfloat16* Bl = Wlo + (size_t)z * WK + bn * Hsz;
    const float* bias = (z == 0) ? bq : (z == 1) ? bk : bv;

    float acc[2][4][4];
    #pragma unroll
    for (int mi = 0; mi < 2; mi++)
        #pragma unroll
        for (int ni = 0; ni < 4; ni++)
            #pragma unroll
            for (int r = 0; r < 4; r++) acc[mi][ni][r] = 0.f;

    gemm_core256(Ahg + bm * Hsz, Alg + bm * Hsz, Bh, Bl, sb, tid, wm, wn, lane, acc);

    const int r0 = lane >> 2;
    const int cc = (lane & 3) * 2;

    if (z == 2) {
        // stage tile as V^T [d][s] in smem (u16, pitch 136), coalesced stores.
        unsigned short* sh = (unsigned short*)smc;          // 64 x 136
        unsigned short* sl = sh + 64 * 136;
        __syncthreads();
        #pragma unroll
        for (int mi = 0; mi < 2; mi++) {
            #pragma unroll
            for (int ni = 0; ni < 4; ni++) {
                int cl = wn * 32 + ni * 8 + cc;             // local d (0..63)
                float2 bsv = *(const float2*)&bias[bn + cl];
                #pragma unroll
                for (int half = 0; half < 2; half++) {
                    int ml = wm * 32 + mi * 16 + r0 + half * 8;   // local s (0..127)
                    float v0 = acc[mi][ni][half * 2 + 0] + bsv.x;
                    float v1 = acc[mi][ni][half * 2 + 1] + bsv.y;
                    unsigned hw, lw;
                    split2_trunc(v0, v1, hw, lw);
                    __nv_bfloat162 h2 = *(__nv_bfloat162*)&hw;
                    __nv_bfloat162 l2 = *(__nv_bfloat162*)&lw;
                    sh[(cl + 0) * 136 + ml] = *(unsigned short*)&h2.x;
                    sh[(cl + 1) * 136 + ml] = *(unsigned short*)&h2.y;
                    sl[(cl + 0) * 136 + ml] = *(unsigned short*)&l2.x;
                    sl[(cl + 1) * 136 + ml] = *(unsigned short*)&l2.y;
                }
            }
        }
        __syncthreads();
        const int hh = (int)(bn >> 7);
        const int dbase = (int)(bn & 127);
        const size_t b_ = bm >> 11, sbase = bm & 2047;
        const size_t rowbase = ((b_ * NH + hh) * (size_t)HD) + dbase;
        #pragma unroll
        for (int i = 0; i < 4; i++) {
            int idx = tid + i * 256;        // 0..1023
            int d = idx >> 4, ch = idx & 15;
            uint4 vh = *(uint4*)(sh + d * 136 + ch * 8);
            uint4 vl = *(uint4*)(sl + d * 136 + ch * 8);
            size_t off = (rowbase + d) * Ssz + sbase + ch * 8;
            *(uint4*)(vth + off) = vh;
            *(uint4*)(vtl + off) = vl;
        }
        return;
    }

    __nv_bfloat16* oh = (z == 0) ? qh : kh;
    __nv_bfloat16* ol = (z == 0) ? ql : kl;
    const float scale = (z == 0) ? QSCALE : 1.f;
    #pragma unroll
    for (int mi = 0; mi < 2; mi++) {
        #pragma unroll
        for (int ni = 0; ni < 4; ni++) {
            int col = (int)bn + wn * 32 + ni * 8 + cc;
            float2 bsv = *(const float2*)&bias[col];
            #pragma unroll
            for (int half = 0; half < 2; half++) {
                size_t m = bm + wm * 32 + mi * 16 + r0 + half * 8;
                float v0 = (acc[mi][ni][half * 2 + 0] + bsv.x) * scale;
                float v1 = (acc[mi][ni][half * 2 + 1] + bsv.y) * scale;
                unsigned hw, lw;
                split2_trunc(v0, v1, hw, lw);
                size_t b_ = m >> 11, s_ = m & 2047;
                int hh = col >> 7, d = col & 127;
                size_t idx = (((b_ * NH + hh) * Ssz) + s_) * HD + d;
                *(unsigned*)(oh + idx) = hw;
                *(unsigned*)(ol + idx) = lw;
            }
        }
    }
}

// Output projection: fp32 result
__global__ void __launch_bounds__(256, 2) gemm_out(
    const __nv_bfloat16* __restrict__ Ahg, const __nv_bfloat16* __restrict__ Alg,
    const __nv_bfloat16* __restrict__ Bh, const __nv_bfloat16* __restrict__ Bl,
    const float* __restrict__ bias, float* __restrict__ outf)
{
    extern __shared__ char smc[];
    const unsigned sb = smem_u32(smc);
    const int tid = threadIdx.x, wid = tid >> 5, lane = tid & 31;
    const int wm = wid >> 1, wn = wid & 1;
    const size_t bm = (size_t)blockIdx.y * 128, bn = (size_t)blockIdx.x * 64;

    float acc[2][4][4];
    #pragma unroll
    for (int mi = 0; mi < 2; mi++)
        #pragma unroll
        for (int ni = 0; ni < 4; ni++)
            #pragma unroll
            for (int r = 0; r < 4; r++) acc[mi][ni][r] = 0.f;

    gemm_core256(Ahg + bm * Hsz, Alg + bm * Hsz, Bh + bn * Hsz, Bl + bn * Hsz,
                 sb, tid, wm, wn, lane, acc);

    const int r0 = lane >> 2;
    const int cc = (lane & 3) * 2;
    #pragma unroll
    for (int mi = 0; mi < 2; mi++) {
        #pragma unroll
        for (int ni = 0; ni < 4; ni++) {
            int col = (int)bn + wn * 32 + ni * 8 + cc;
            float2 bsv = *(const float2*)&bias[col];
            #pragma unroll
            for (int half = 0; half < 2; half++) {
                size_t m = bm + wm * 32 + mi * 16 + r0 + half * 8;
                *(float2*)(outf + m * Hsz + col) =
                    make_float2(acc[mi][ni][half * 2 + 0] + bsv.x,
                                acc[mi][ni][half * 2 + 1] + bsv.y);
            }
        }
    }
}

// ---------------- attention: 64 q-rows, 128 thr, 2 CTAs/SM -----------------
// 4 warps x 16 rows; 32-key tiles double-buffered. No-max softmax via exp2.
#define TK 32
#define S_QH 0
#define S_QL 17408                 // 64*272
#define S_KV0 34816
#define S_KH 0
#define S_KL 8704                  // 32*272
#define S_VH 17408
#define S_VL 27648                 // +128*80
#define KVBUF 37888
#define A_SMEM (S_KV0 + 2*KVBUF)   // 110592

__device__ __forceinline__ void attn_issue_kv(
    unsigned sb, int buf, int t, int tid,
    const __nv_bfloat16* kh, const __nv_bfloat16* kl,
    const __nv_bfloat16* vth, const __nv_bfloat16* vtl)
{
    unsigned kb = sb + S_KV0 + buf * KVBUF;
    #pragma unroll
    for (int i = 0; i < 4; i++) {
        int idx = tid + i * 128; int row = idx >> 4, ch = idx & 15;   // 32 x 16
        cp16(kb + S_KH + row * 272 + ch * 16, kh + (size_t)(t * TK + row) * HD + ch * 8);
        cp16(kb + S_KL + row * 272 + ch * 16, kl + (size_t)(t * TK + row) * HD + ch * 8);
    }
    #pragma unroll
    for (int i = 0; i < 4; i++) {
        int idx = tid + i * 128; int row = idx >> 2, ch = idx & 3;    // 128 x 4
        cp16(kb + S_VH + row * 80 + ch * 16, vth + (size_t)row * Ssz + t * TK + ch * 8);
        cp16(kb + S_VL + row * 80 + ch * 16, vtl + (size_t)row * Ssz + t * TK + ch * 8);
    }
    CP_COMMIT();
}

__global__ void __launch_bounds__(128, 2) attn_mma(
    const __nv_bfloat16* __restrict__ Qhg, const __nv_bfloat16* __restrict__ Qlg,
    const __nv_bfloat16* __restrict__ Khg, const __nv_bfloat16* __restrict__ Klg,
    const __nv_bfloat16* __restrict__ Vthg, const __nv_bfloat16* __restrict__ Vtlg,
    __nv_bfloat16* __restrict__ AOh, __nv_bfloat16* __restrict__ AOl)
{
    extern __shared__ char smc[];
    const unsigned sb = smem_u32(smc);
    const int tid = threadIdx.x, w = tid >> 5, lane = tid & 31;
    const int bh = blockIdx.y, q0 = blockIdx.x * 64;

    const __nv_bfloat16* qh = Qhg + ((size_t)bh * Ssz + q0) * HD;
    const __nv_bfloat16* ql = Qlg + ((size_t)bh * Ssz + q0) * HD;
    const __nv_bfloat16* kh = Khg + (size_t)bh * Ssz * HD;
    const __nv_bfloat16* kl = Klg + (size_t)bh * Ssz * HD;
    const __nv_bfloat16* vth = Vthg + (size_t)bh * HD * Ssz;
    const __nv_bfloat16* vtl = Vtlg + (size_t)bh * HD * Ssz;

    // Q staging: 64 rows x 16 chunks, hi+lo
    #pragma unroll
    for (int i = 0; i < 8; i++) {
        int idx = tid + i * 128; int row = idx >> 4, ch = idx & 15;
        cp16(sb + S_QH + row * 272 + ch * 16, qh + (size_t)row * HD + ch * 8);
        cp16(sb + S_QL + row * 272 + ch * 16, ql + (size_t)row * HD + ch * 8);
    }
    attn_issue_kv(sb, 0, 0, tid, kh, kl, vth, vtl);

    float lacc0 = 0.f, lacc1 = 0.f;
    float o[16][4];
    #pragma unroll
    for (int nf = 0; nf < 16; nf++)
        #pragma unroll
        for (int r = 0; r < 4; r++) o[nf][r] = 0.f;

    const unsigned lrow = (unsigned)(lane & 15);
    const unsigned lquad = (unsigned)((lane >> 4) * 16);
    const unsigned aqh = sb + S_QH + (w * 16 + lrow) * 272 + lquad;
    const unsigned aql = sb + S_QL + (w * 16 + lrow) * 272 + lquad;

    #pragma unroll 1
    for (int t = 0; t < Ssz / TK; t++) {
        const int buf = t & 1;
        if (t < Ssz / TK - 1) { attn_issue_kv(sb, buf ^ 1, t + 1, tid, kh, kl, vth, vtl); CP_WAIT1(); }
        else                  { CP_WAIT0(); }
        __syncthreads();

        const unsigned kb = sb + S_KV0 + buf * KVBUF;

        float s[4][4];
        #pragma unroll
        for (int nf = 0; nf < 4; nf++)
            #pragma unroll
            for (int r = 0; r < 4; r++) s[nf][r] = 0.f;

        // interleaved ldsm/MMA
        #pragma unroll
        for (int kc = 0; kc < 8; kc++) {
            unsigned ah[4], al[4], bh4[2][4], bl4[2][4];
            ldsm_x4(ah[0], ah[1], ah[2], ah[3], aqh + kc * 32);
            #pragma unroll
            for (int bi = 0; bi < 2; bi++) {
                unsigned kbr = (unsigned)(bi * 16 + lrow) * 272 + lquad + kc * 32;
                ldsm_x4(bh4[bi][0], bh4[bi][1], bh4[bi][2], bh4[bi][3], kb + S_KH + kbr);
            }
            #pragma unroll
            for (int bi = 0; bi < 2; bi++) {
                mma16816(s[2*bi],   ah[0],ah[1],ah[2],ah[3], bh4[bi][0], bh4[bi][2]);
                mma16816(s[2*bi+1], ah[0],ah[1],ah[2],ah[3], bh4[bi][1], bh4[bi][3]);
            }
            #pragma unroll
            for (int bi = 0; bi < 2; bi++) {
                unsigned kbr = (unsigned)(bi * 16 + lrow) * 272 + lquad + kc * 32;
                ldsm_x4(bl4[bi][0], bl4[bi][1], bl4[bi][2], bl4[bi][3], kb + S_KL + kbr);
            }
            #pragma unroll
            for (int bi = 0; bi < 2; bi++) {
                mma16816(s[2*bi],   ah[0],ah[1],ah[2],ah[3], bl4[bi][0], bl4[bi][2]);
                mma16816(s[2*bi+1], ah[0],ah[1],ah[2],ah[3], bl4[bi][1], bl4[bi][3]);
            }
            ldsm_x4(al[0], al[1], al[2], al[3], aql + kc * 32);
            #pragma unroll
            for (int bi = 0; bi < 2; bi++) {
                mma16816(s[2*bi],   al[0],al[1],al[2],al[3], bh4[bi][0], bh4[bi][2]);
                mma16816(s[2*bi+1], al[0],al[1],al[2],al[3], bh4[bi][1], bh4[bi][3]);
            }
        }

        // ---- softmax numerator: p = exp2(s), per-lane l accumulation ----
        #pragma unroll
        for (int nf = 0; nf < 4; nf++) {
            s[nf][0] = exp2f(s[nf][0]); lacc0 += s[nf][0];
            s[nf][1] = exp2f(s[nf][1]); lacc0 += s[nf][1];
            s[nf][2] = exp2f(s[nf][2]); lacc1 += s[nf][2];
            s[nf][3] = exp2f(s[nf][3]); lacc1 += s[nf][3];
        }

        // ---- P -> bf16 split A-frags ----
        unsigned pah[2][4], pal[2][4];
        #pragma unroll
        for (int kc2 = 0; kc2 < 2; kc2++) {
            #pragma unroll
            for (int r = 0; r < 4; r++) {
                int nf = 2 * kc2 + (r >> 1);
                float v0 = s[nf][(r & 1) * 2], v1 = s[nf][(r & 1) * 2 + 1];
                split2_trunc(v0, v1, pah[kc2][r], pal[kc2][r]);
            }
        }

        // ---- O += P V (fused 3-pass), V-frags double-buffered ----
        #pragma unroll
        for (int kc2 = 0; kc2 < 2; kc2++) {
            unsigned vh4[2][4], vl4[2][4];
            {
                unsigned vr = lrow * 80 + lquad + kc2 * 32;
                ldsm_x4(vh4[0][0], vh4[0][1], vh4[0][2], vh4[0][3], kb + S_VH + vr);
                ldsm_x4(vl4[0][0], vl4[0][1], vl4[0][2], vl4[0][3], kb + S_VL + vr);
            }
            #pragma unroll
            for (int nf2 = 0; nf2 < 8; nf2++) {
                const int cur = nf2 & 1, nxt = cur ^ 1;
                if (nf2 < 7) {
                    unsigned vr = (unsigned)((nf2 + 1) * 16 + lrow) * 80 + lquad + kc2 * 32;
                    ldsm_x4(vh4[nxt][0], vh4[nxt][1], vh4[nxt][2], vh4[nxt][3], kb + S_VH + vr);
                    ldsm_x4(vl4[nxt][0], vl4[nxt][1], vl4[nxt][2], vl4[nxt][3], kb + S_VL + vr);
                }
                mma16816(o[2*nf2],   pah[kc2][0],pah[kc2][1],pah[kc2][2],pah[kc2][3], vh4[cur][0], vh4[cur][2]);
                mma16816(o[2*nf2+1], pah[kc2][0],pah[kc2][1],pah[kc2][2],pah[kc2][3], vh4[cur][1], vh4[cur][3]);
                mma16816(o[2*nf2],   pah[kc2][0],pah[kc2][1],pah[kc2][2],pah[kc2][3], vl4[cur][0], vl4[cur][2]);
                mma16816(o[2*nf2+1], pah[kc2][0],pah[kc2][1],pah[kc2][2],pah[kc2][3], vl4[cur][1], vl4[cur][3]);
                mma16816(o[2*nf2],   pal[kc2][0],pal[kc2][1],pal[kc2][2],pal[kc2][3], vh4[cur][0], vh4[cur][2]);
                mma16816(o[2*nf2+1], pal[kc2][0],pal[kc2][1],pal[kc2][2],pal[kc2][3], vh4[cur][1], vh4[cur][3]);
            }
        }
        __syncthreads();
    }

    // ---- final l reduction across the 4 lanes of each quad ----
    float l0 = lacc0, l1 = lacc1;
    l0 += __shfl_xor_sync(0xffffffffu, l0, 1);
    l0 += __shfl_xor_sync(0xffffffffu, l0, 2);
    l1 += __shfl_xor_sync(0xffffffffu, l1, 1);
    l1 += __shfl_xor_sync(0xffffffffu, l1, 2);

    // ---- epilogue: normalize, split, store to ao [B,S,H] ----
    float il0 = 1.f / l0, il1 = 1.f / l1;
    const int b = bh >> 4, h = bh & 15;
    size_t srow = (size_t)q0 + w * 16 + (lane >> 2);
    size_t base0 = ((size_t)b * Ssz + srow) * Hsz + h * 128 + (lane & 3) * 2;
    size_t base1 = base0 + 8 * (size_t)Hsz;
    #pragma unroll
    for (int nf = 0; nf < 16; nf++) {
        unsigned hw, lw;
        split2_trunc(o[nf][0] * il0, o[nf][1] * il0, hw, lw);
        *(unsigned*)(AOh + base0 + nf * 8) = hw;
        *(unsigned*)(AOl + base0 + nf * 8) = lw;
        split2_trunc(o[nf][2] * il1, o[nf][3] * il1, hw, lw);
        *(unsigned*)(AOh + base1 + nf * 8) = hw;
        *(unsigned*)(AOl + base1 + nf * 8) = lw;
    }
}

// ---------------------------------------------------------------------------
extern "C" void kernel_launch(void* const* d_in, const int* in_sizes, int n_in,
                              void* d_out, int out_size)
{
    const float* x  = (const float*)d_in[0];
    const float* Wq = (const float*)d_in[1];
    const float* bq = (const float*)d_in[2];
    const float* Wk = (const float*)d_in[3];
    const float* bk = (const float*)d_in[4];
    const float* Wv = (const float*)d_in[5];
    const float* bv = (const float*)d_in[6];
    const float* Wo = (const float*)d_in[7];
    const float* bo = (const float*)d_in[8];
    float* out = (float*)d_out;

    __nv_bfloat16 *xhi, *xlo, *whi, *wlo, *qh, *ql, *kh, *kl, *vth, *vtl, *aoh, *aol;
    cudaGetSymbolAddress((void**)&xhi, g_xhi);
    cudaGetSymbolAddress((void**)&xlo, g_xlo);
    cudaGetSymbolAddress((void**)&whi, g_whi);
    cudaGetSymbolAddress((void**)&wlo, g_wlo);
    cudaGetSymbolAddress((void**)&qh,  g_qh);
    cudaGetSymbolAddress((void**)&ql,  g_ql);
    cudaGetSymbolAddress((void**)&kh,  g_kh);
    cudaGetSymbolAddress((void**)&kl,  g_kl);
    cudaGetSymbolAddress((void**)&vth, g_vth);
    cudaGetSymbolAddress((void**)&vtl, g_vtl);
    cudaGetSymbolAddress((void**)&aoh, g_aoh);
    cudaGetSymbolAddress((void**)&aol, g_aol);

    cudaFuncSetAttribute(gemm_qkv, cudaFuncAttributeMaxDynamicSharedMemorySize, GSMEM);
    cudaFuncSetAttribute(gemm_out, cudaFuncAttributeMaxDynamicSharedMemorySize, GSMEM);
    cudaFuncSetAttribute(attn_mma, cudaFuncAttributeMaxDynamicSharedMemorySize, A_SMEM);

    dim3 tgrid(Hsz / 32, Hsz / 32, 4), tblk(32, 8);
    tsplit4_kernel<<<tgrid, tblk>>>(Wq, Wk, Wv, Wo, whi, wlo);
    split_kernel<<<2048, 256>>>(x, xhi, xlo, MK);

    dim3 qkvgrid(Hsz / 64, Msz / 128, 3);    // (32, 64, 3)
    gemm_qkv<<<qkvgrid, 256, GSMEM>>>(xhi, xlo, whi, wlo, bq, bk, bv,
                                      qh, ql, kh, kl, vth, vtl);

    dim3 agrid(Ssz / 64, Bsz * NH);          // (32, 64)
    attn_mma<<<agrid, 128, A_SMEM>>>(qh, ql, kh, kl, vth, vtl, aoh, aol);

    dim3 ogrid(Hsz / 64, Msz / 128);         // (32, 64)
    gemm_out<<<ogrid, 256, GSMEM>>>(aoh, aol, whi + 3 * WK, wlo + 3 * WK, bo, out);
}

// round 16
// speedup vs baseline: 1.0431x; 1.0431x over previous
#include <cuda_runtime.h>
#include <cuda_bf16.h>
#include <math.h>

// Problem shape
#define Bsz 4
#define Ssz 2048
#define Hsz 2048
#define NH  16
#define HD  128
#define Msz (Bsz*Ssz)          // 8192
#define MK  ((size_t)Msz*Hsz)  // 16,777,216
#define WK  ((size_t)Hsz*Hsz)  // 4,194,304

// 1/sqrt(128) * log2(e)  (attention uses exp2; scale folded into Q)
#define QSCALE 0.12751949974651278f

// ---------------- scratch (__device__ globals; no cudaMalloc allowed) ------
__device__ __nv_bfloat16 g_xhi[MK], g_xlo[MK];
__device__ __nv_bfloat16 g_whi[4][WK], g_wlo[4][WK];   // W^T split, [N][K]
__device__ __nv_bfloat16 g_qh[MK], g_ql[MK];           // [B*nh][S][hd], scale folded
__device__ __nv_bfloat16 g_kh[MK], g_kl[MK];           // [B*nh][S][hd]
__device__ __nv_bfloat16 g_vth[MK], g_vtl[MK];         // V^T: [B*nh][hd][S]
__device__ __nv_bfloat16 g_aoh[MK], g_aol[MK];         // [B,S,H] split

// ---------------- PTX helpers ---------------------------------------------
__device__ __forceinline__ unsigned smem_u32(const void* p) {
    unsigned a;
    asm("{ .reg .u64 t; cvta.to.shared.u64 t, %1; cvt.u32.u64 %0, t; }"
        : "=r"(a) : "l"(p));
    return a;
}
__device__ __forceinline__ void ldsm_x4(unsigned& r0, unsigned& r1,
                                        unsigned& r2, unsigned& r3, unsigned a) {
    asm volatile("ldmatrix.sync.aligned.m8n8.x4.shared.b16 {%0,%1,%2,%3}, [%4];"
                 : "=r"(r0), "=r"(r1), "=r"(r2), "=r"(r3) : "r"(a));
}
__device__ __forceinline__ void mma16816(float* c, unsigned a0, unsigned a1,
                                         unsigned a2, unsigned a3,
                                         unsigned b0, unsigned b1) {
    asm volatile(
        "mma.sync.aligned.m16n8k16.row.col.f32.bf16.bf16.f32 "
        "{%0,%1,%2,%3}, {%4,%5,%6,%7}, {%8,%9}, {%0,%1,%2,%3};"
        : "+f"(c[0]), "+f"(c[1]), "+f"(c[2]), "+f"(c[3])
        : "r"(a0), "r"(a1), "r"(a2), "r"(a3), "r"(b0), "r"(b1));
}
__device__ __forceinline__ void cp16(unsigned dst, const void* src) {
    asm volatile("{ .reg .u64 g; cvta.to.global.u64 g, %1;\n\t"
                 "cp.async.cg.shared.global [%0], [g], 16; }"
                 :: "r"(dst), "l"(src) : "memory");
}
#define CP_COMMIT() asm volatile("cp.async.commit_group;" ::: "memory")
#define CP_WAIT1()  asm volatile("cp.async.wait_group 1;" ::: "memory")
#define CP_WAIT0()  asm volatile("cp.async.wait_group 0;" ::: "memory")

// truncating split: hi = top 16 bits (PRMT), lo = rounded exact residual.
__device__ __forceinline__ void split2_trunc(float v0, float v1, unsigned& hi, unsigned& lo) {
    unsigned u0 = __float_as_uint(v0), u1 = __float_as_uint(v1);
    hi = __byte_perm(u0, u1, 0x7632);
    float r0 = v0 - __uint_as_float(u0 & 0xffff0000u);
    float r1 = v1 - __uint_as_float(u1 & 0xffff0000u);
    __nv_bfloat162 l = __float22bfloat162_rn(make_float2(r0, r1));
    lo = *(unsigned*)&l;
}

// ---------------- conversion kernels --------------------------------------
__global__ void split_kernel(const float* __restrict__ in,
                             __nv_bfloat16* __restrict__ hi,
                             __nv_bfloat16* __restrict__ lo, size_t n) {
    for (size_t i = blockIdx.x * blockDim.x + threadIdx.x; i < n;
         i += (size_t)gridDim.x * blockDim.x) {
        float f = in[i];
        __nv_bfloat16 h = __float2bfloat16(f);
        hi[i] = h;
        lo[i] = __float2bfloat16(f - __bfloat162float(h));
    }
}

// All 4 weight transposes in one launch: W[K][N] -> Wt_hi/lo[N][K], z selects W
__global__ void tsplit4_kernel(const float* __restrict__ W0, const float* __restrict__ W1,
                               const float* __restrict__ W2, const float* __restrict__ W3,
                               __nv_bfloat16* __restrict__ hib,
                               __nv_bfloat16* __restrict__ lob) {
    __shared__ float tile[32][33];
    const float* W = (blockIdx.z == 0) ? W0 : (blockIdx.z == 1) ? W1
                     : (blockIdx.z == 2) ? W2 : W3;
    __nv_bfloat16* hi = hib + (size_t)blockIdx.z * WK;
    __nv_bfloat16* lo = lob + (size_t)blockIdx.z * WK;
    int bx = blockIdx.x * 32, by = blockIdx.y * 32;
    int tx = threadIdx.x, ty = threadIdx.y;
    #pragma unroll
    for (int i = 0; i < 32; i += 8)
        tile[ty + i][tx] = W[(size_t)(by + ty + i) * Hsz + bx + tx];
    __syncthreads();
    #pragma unroll
    for (int i = 0; i < 32; i += 8) {
        int n = bx + ty + i, k = by + tx;
        float f = tile[tx][ty + i];
        __nv_bfloat16 h = __float2bfloat16(f);
        hi[(size_t)n * Hsz + k] = h;
        lo[(size_t)n * Hsz + k] = __float2bfloat16(f - __bfloat162float(h));
    }
}

// ---------------- mma.sync split-bf16 GEMM (256 thr, 2 CTAs/SM) ------------
// Block 128(M)x64(N), K-chunk 64, 8 warps 4(m)x2(n), warp tile 32x32.
#define TPITCH 144
#define A_TILE (128*TPITCH)        // 18432
#define B_TILE (64*TPITCH)         // 9216
#define BUF_B  (2*A_TILE + 2*B_TILE)  // 55296
#define GSMEM  (2*BUF_B)           // 110592

__device__ __forceinline__ void gemm_issue256(
    const __nv_bfloat16* Ah, const __nv_bfloat16* Al,
    const __nv_bfloat16* Bh, const __nv_bfloat16* Bl,
    unsigned sb, int buf, int k0, int tid)
{
    const unsigned base = sb + buf * BUF_B;
    #pragma unroll
    for (int i = 0; i < 4; i++) {
        int idx = tid + i * 256;           // 0..1023
        int row = idx >> 3, ch = idx & 7;
        unsigned off = row * TPITCH + ch * 16;
        const size_t g = (size_t)row * Hsz + k0 + ch * 8;
        cp16(base + off, Ah + g);
        cp16(base + A_TILE + off, Al + g);
    }
    #pragma unroll
    for (int i = 0; i < 2; i++) {
        int idx = tid + i * 256;           // 0..511
        int row = idx >> 3, ch = idx & 7;
        unsigned off = row * TPITCH + ch * 16;
        const size_t g = (size_t)row * Hsz + k0 + ch * 8;
        cp16(base + 2 * A_TILE + off, Bh + g);
        cp16(base + 2 * A_TILE + B_TILE + off, Bl + g);
    }
    CP_COMMIT();
}

// core mainloop: fills acc[2][4][4] for warp tile (wm*32, wn*32)
__device__ __forceinline__ void gemm_core256(
    const __nv_bfloat16* Ah, const __nv_bfloat16* Al,
    const __nv_bfloat16* Bh, const __nv_bfloat16* Bl,
    unsigned sb, int tid, int wm, int wn, int lane, float acc[2][4][4])
{
    const unsigned lm_off = (unsigned)((lane & 15) * TPITCH + (lane >> 4) * 16);

    gemm_issue256(Ah, Al, Bh, Bl, sb, 0, 0, tid);

    #pragma unroll 1
    for (int c = 0; c < 32; c++) {
        const int buf = c & 1;
        if (c < 31) { gemm_issue256(Ah, Al, Bh, Bl, sb, buf ^ 1, (c + 1) * 64, tid); CP_WAIT1(); }
        else        { CP_WAIT0(); }
        __syncthreads();

        const unsigned base   = sb + buf * BUF_B;
        const unsigned a_hi_b = base + (unsigned)(wm * 32 * TPITCH) + lm_off;
        const unsigned a_lo_b = a_hi_b + A_TILE;
        const unsigned b_hi_b = base + 2u * A_TILE + (unsigned)(wn * 32 * TPITCH) + lm_off;
        const unsigned b_lo_b = b_hi_b + B_TILE;

        #pragma unroll
        for (int ks = 0; ks < 4; ks++) {
            const unsigned ko = ks * 32;
            unsigned ah[2][4], al[2][4], bh[2][4], bl[2][4];
            #pragma unroll
            for (int mi = 0; mi < 2; mi++)
                ldsm_x4(ah[mi][0], ah[mi][1], ah[mi][2], ah[mi][3],
                        a_hi_b + mi * 16 * TPITCH + ko);
            #pragma unroll
            for (int bi = 0; bi < 2; bi++)
                ldsm_x4(bh[bi][0], bh[bi][1], bh[bi][2], bh[bi][3],
                        b_hi_b + bi * 16 * TPITCH + ko);
            #pragma unroll
            for (int mi = 0; mi < 2; mi++)
                #pragma unroll
                for (int ni = 0; ni < 4; ni++)
                    mma16816(acc[mi][ni], ah[mi][0], ah[mi][1], ah[mi][2], ah[mi][3],
                             bh[ni >> 1][ni & 1], bh[ni >> 1][(ni & 1) + 2]);
            #pragma unroll
            for (int bi = 0; bi < 2; bi++)
                ldsm_x4(bl[bi][0], bl[bi][1], bl[bi][2], bl[bi][3],
                        b_lo_b + bi * 16 * TPITCH + ko);
            #pragma unroll
            for (int mi = 0; mi < 2; mi++)
                #pragma unroll
                for (int ni = 0; ni < 4; ni++)
                    mma16816(acc[mi][ni], ah[mi][0], ah[mi][1], ah[mi][2], ah[mi][3],
                             bl[ni >> 1][ni & 1], bl[ni >> 1][(ni & 1) + 2]);
            #pragma unroll
            for (int mi = 0; mi < 2; mi++)
                ldsm_x4(al[mi][0], al[mi][1], al[mi][2], al[mi][3],
                        a_lo_b + mi * 16 * TPITCH + ko);
            #pragma unroll
            for (int mi = 0; mi < 2; mi++)
                #pragma unroll
                for (int ni = 0; ni < 4; ni++)
                    mma16816(acc[mi][ni], al[mi][0], al[mi][1], al[mi][2], al[mi][3],
                             bh[ni >> 1][ni & 1], bh[ni >> 1][(ni & 1) + 2]);
        }
        __syncthreads();
    }
}

// Fused Q/K/V projection: blockIdx.z = 0(Q) 1(K) 2(V^T)
__global__ void __launch_bounds__(256, 2) gemm_qkv(
    const __nv_bfloat16* __restrict__ Ahg, const __nv_bfloat16* __restrict__ Alg,
    const __nv_bfloat16* __restrict__ Whi, const __nv_bfloat16* __restrict__ Wlo,
    const float* __restrict__ bq, const float* __restrict__ bk,
    const float* __restrict__ bv,
    __nv_bfloat16* __restrict__ qh, __nv_bfloat16* __restrict__ ql,
    __nv_bfloat16* __restrict__ kh, __nv_bfloat16* __restrict__ kl,
    __nv_bfloat16* __restrict__ vth, __nv_bfloat16* __restrict__ vtl)
{
    extern __shared__ char smc[];
    const unsigned sb = smem_u32(smc);
    const int tid = threadIdx.x, wid = tid >> 5, lane = tid & 31;
    const int wm = wid >> 1, wn = wid & 1;        // 4 x 2 warp grid
    const int z = blockIdx.z;
    const size_t bm = (size_t)blockIdx.y * 128, bn = (size_t)blockIdx.x * 64;

    const __nv_bfloat16* Bh = Whi + (size_t)z * WK + bn * Hsz;
    const __nv_bfloat16* Bl = Wlo + (size_t)z * WK + bn * Hsz;
    const float* bias = (z == 0) ? bq : (z == 1) ? bk : bv;

    float acc[2][4][4];
    #pragma unroll
    for (int mi = 0; mi < 2; mi++)
        #pragma unroll
        for (int ni = 0; ni < 4; ni++)
            #pragma unroll
            for (int r = 0; r < 4; r++) acc[mi][ni][r] = 0.f;

    gemm_core256(Ahg + bm * Hsz, Alg + bm * Hsz, Bh, Bl, sb, tid, wm, wn, lane, acc);

    const int r0 = lane >> 2;
    const int cc = (lane & 3) * 2;

    if (z == 2) {
        // stage tile as V^T [d][s] in smem (u16, pitch 136), coalesced stores.
        unsigned short* sh = (unsigned short*)smc;          // 64 x 136
        unsigned short* sl = sh + 64 * 136;
        __syncthreads();
        #pragma unroll
        for (int mi = 0; mi < 2; mi++) {
            #pragma unroll
            for (int ni = 0; ni < 4; ni++) {
                int cl = wn * 32 + ni * 8 + cc;             // local d (0..63)
                float2 bsv = *(const float2*)&bias[bn + cl];
                #pragma unroll
                for (int half = 0; half < 2; half++) {
                    int ml = wm * 32 + mi * 16 + r0 + half * 8;   // local s (0..127)
                    float v0 = acc[mi][ni][half * 2 + 0] + bsv.x;
                    float v1 = acc[mi][ni][half * 2 + 1] + bsv.y;
                    unsigned hw, lw;
                    split2_trunc(v0, v1, hw, lw);
                    __nv_bfloat162 h2 = *(__nv_bfloat162*)&hw;
                    __nv_bfloat162 l2 = *(__nv_bfloat162*)&lw;
                    sh[(cl + 0) * 136 + ml] = *(unsigned short*)&h2.x;
                    sh[(cl + 1) * 136 + ml] = *(unsigned short*)&h2.y;
                    sl[(cl + 0) * 136 + ml] = *(unsigned short*)&l2.x;
                    sl[(cl + 1) * 136 + ml] = *(unsigned short*)&l2.y;
                }
            }
        }
        __syncthreads();
        const int hh = (int)(bn >> 7);
        const int dbase = (int)(bn & 127);
        const size_t b_ = bm >> 11, sbase = bm & 2047;
        const size_t rowbase = ((b_ * NH + hh) * (size_t)HD) + dbase;
        #pragma unroll
        for (int i = 0; i < 4; i++) {
            int idx = tid + i * 256;        // 0..1023
            int d = idx >> 4, ch = idx & 15;
            uint4 vh = *(uint4*)(sh + d * 136 + ch * 8);
            uint4 vl = *(uint4*)(sl + d * 136 + ch * 8);
            size_t off = (rowbase + d) * Ssz + sbase + ch * 8;
            *(uint4*)(vth + off) = vh;
            *(uint4*)(vtl + off) = vl;
        }
        return;
    }

    __nv_bfloat16* oh = (z == 0) ? qh : kh;
    __nv_bfloat16* ol = (z == 0) ? ql : kl;
    const float scale = (z == 0) ? QSCALE : 1.f;
    #pragma unroll
    for (int mi = 0; mi < 2; mi++) {
        #pragma unroll
        for (int ni = 0; ni < 4; ni++) {
            int col = (int)bn + wn * 32 + ni * 8 + cc;
            float2 bsv = *(const float2*)&bias[col];
            #pragma unroll
            for (int half = 0; half < 2; half++) {
                size_t m = bm + wm * 32 + mi * 16 + r0 + half * 8;
                float v0 = (acc[mi][ni][half * 2 + 0] + bsv.x) * scale;
                float v1 = (acc[mi][ni][half * 2 + 1] + bsv.y) * scale;
                unsigned hw, lw;
                split2_trunc(v0, v1, hw, lw);
                size_t b_ = m >> 11, s_ = m & 2047;
                int hh = col >> 7, d = col & 127;
                size_t idx = (((b_ * NH + hh) * Ssz) + s_) * HD + d;
                *(unsigned*)(oh + idx) = hw;
                *(unsigned*)(ol + idx) = lw;
            }
        }
    }
}

// Output projection: fp32 result
__global__ void __launch_bounds__(256, 2) gemm_out(
    const __nv_bfloat16* __restrict__ Ahg, const __nv_bfloat16* __restrict__ Alg,
    const __nv_bfloat16* __restrict__ Bh, const __nv_bfloat16* __restrict__ Bl,
    const float* __restrict__ bias, float* __restrict__ outf)
{
    extern __shared__ char smc[];
    const unsigned sb = smem_u32(smc);
    const int tid = threadIdx.x, wid = tid >> 5, lane = tid & 31;
    const int wm = wid >> 1, wn = wid & 1;
    const size_t bm = (size_t)blockIdx.y * 128, bn = (size_t)blockIdx.x * 64;

    float acc[2][4][4];
    #pragma unroll
    for (int mi = 0; mi < 2; mi++)
        #pragma unroll
        for (int ni = 0; ni < 4; ni++)
            #pragma unroll
            for (int r = 0; r < 4; r++) acc[mi][ni][r] = 0.f;

    gemm_core256(Ahg + bm * Hsz, Alg + bm * Hsz, Bh + bn * Hsz, Bl + bn * Hsz,
                 sb, tid, wm, wn, lane, acc);

    const int r0 = lane >> 2;
    const int cc = (lane & 3) * 2;
    #pragma unroll
    for (int mi = 0; mi < 2; mi++) {
        #pragma unroll
        for (int ni = 0; ni < 4; ni++) {
            int col = (int)bn + wn * 32 + ni * 8 + cc;
            float2 bsv = *(const float2*)&bias[col];
            #pragma unroll
            for (int half = 0; half < 2; half++) {
                size_t m = bm + wm * 32 + mi * 16 + r0 + half * 8;
                *(float2*)(outf + m * Hsz + col) =
                    make_float2(acc[mi][ni][half * 2 + 0] + bsv.x,
                                acc[mi][ni][half * 2 + 1] + bsv.y);
            }
        }
    }
}

// ---------------- attention: mma.sync bf16 split, no-max softmax -----------
// Block: 128 q-rows of one head, 8 warps x 16 rows. 64-key tiles, double-buffered.
// Q-hi fragments hoisted to registers (constant across all tiles).
#define S_QH 0
#define S_QL 34816                 // 128*272
#define S_KV0 69632
#define S_KH 0
#define S_KL 17408                 // 64*272
#define S_VH 34816
#define S_VL 53248                 // +128*144
#define KVBUF 71680
#define A_SMEM (S_KV0 + 2*KVBUF)   // 212992

__device__ __forceinline__ void attn_issue_kv(
    unsigned sb, int buf, int t, int tid,
    const __nv_bfloat16* kh, const __nv_bfloat16* kl,
    const __nv_bfloat16* vth, const __nv_bfloat16* vtl)
{
    unsigned kb = sb + S_KV0 + buf * KVBUF;
    #pragma unroll
    for (int i = 0; i < 4; i++) {
        int idx = tid + i * 256; int row = idx >> 4, ch = idx & 15;
        cp16(kb + S_KH + row * 272 + ch * 16, kh + (size_t)(t * 64 + row) * HD + ch * 8);
        cp16(kb + S_KL + row * 272 + ch * 16, kl + (size_t)(t * 64 + row) * HD + ch * 8);
    }
    #pragma unroll
    for (int i = 0; i < 4; i++) {
        int idx = tid + i * 256; int row = idx >> 3, ch = idx & 7;
        cp16(kb + S_VH + row * 144 + ch * 16, vth + (size_t)row * Ssz + t * 64 + ch * 8);
        cp16(kb + S_VL + row * 144 + ch * 16, vtl + (size_t)row * Ssz + t * 64 + ch * 8);
    }
    CP_COMMIT();
}

__global__ void __launch_bounds__(256, 1) attn_mma(
    const __nv_bfloat16* __restrict__ Qhg, const __nv_bfloat16* __restrict__ Qlg,
    const __nv_bfloat16* __restrict__ Khg, const __nv_bfloat16* __restrict__ Klg,
    const __nv_bfloat16* __restrict__ Vthg, const __nv_bfloat16* __restrict__ Vtlg,
    __nv_bfloat16* __restrict__ AOh, __nv_bfloat16* __restrict__ AOl)
{
    extern __shared__ char smc[];
    const unsigned sb = smem_u32(smc);
    const int tid = threadIdx.x, w = tid >> 5, lane = tid & 31;
    const int bh = blockIdx.y, q0 = blockIdx.x * 128;

    const __nv_bfloat16* qh = Qhg + ((size_t)bh * Ssz + q0) * HD;
    const __nv_bfloat16* ql = Qlg + ((size_t)bh * Ssz + q0) * HD;
    const __nv_bfloat16* kh = Khg + (size_t)bh * Ssz * HD;
    const __nv_bfloat16* kl = Klg + (size_t)bh * Ssz * HD;
    const __nv_bfloat16* vth = Vthg + (size_t)bh * HD * Ssz;
    const __nv_bfloat16* vtl = Vtlg + (size_t)bh * HD * Ssz;

    #pragma unroll
    for (int i = 0; i < 8; i++) {
        int idx = tid + i * 256; int row = idx >> 4, ch = idx & 15;
        cp16(sb + S_QH + row * 272 + ch * 16, qh + (size_t)row * HD + ch * 8);
        cp16(sb + S_QL + row * 272 + ch * 16, ql + (size_t)row * HD + ch * 8);
    }
    attn_issue_kv(sb, 0, 0, tid, kh, kl, vth, vtl);   // Q + KV0 in group 0

    const unsigned lrow = (unsigned)(lane & 15);
    const unsigned lquad = (unsigned)((lane >> 4) * 16);
    const unsigned aqh = sb + S_QH + (w * 16 + lrow) * 272 + lquad;
    const unsigned aql = sb + S_QL + (w * 16 + lrow) * 272 + lquad;

    // wait for Q + KV0; hoist constant Q-hi fragments into registers
    CP_WAIT0();
    __syncthreads();
    unsigned qfh[8][4];
    #pragma unroll
    for (int kc = 0; kc < 8; kc++)
        ldsm_x4(qfh[kc][0], qfh[kc][1], qfh[kc][2], qfh[kc][3], aqh + kc * 32);

    float lacc0 = 0.f, lacc1 = 0.f;
    float o[16][4];
    #pragma unroll
    for (int nf = 0; nf < 16; nf++)
        #pragma unroll
        for (int r = 0; r < 4; r++) o[nf][r] = 0.f;

    #pragma unroll 1
    for (int t = 0; t < 32; t++) {
        const int buf = t & 1;
        if (t < 31) { attn_issue_kv(sb, buf ^ 1, t + 1, tid, kh, kl, vth, vtl); CP_WAIT1(); }
        else        { CP_WAIT0(); }
        __syncthreads();

        const unsigned kb = sb + S_KV0 + buf * KVBUF;

        float s[8][4];
        #pragma unroll
        for (int nf = 0; nf < 8; nf++)
            #pragma unroll
            for (int r = 0; r < 4; r++) s[nf][r] = 0.f;

        // interleaved ldsm/MMA; Q-hi from registers
        #pragma unroll
        for (int kc = 0; kc < 8; kc++) {
            unsigned al[4], bh4[4][4], bl4[4][4];
            #pragma unroll
            for (int bi = 0; bi < 4; bi++) {
                unsigned kbr = (unsigned)(bi * 16 + lrow) * 272 + lquad + kc * 32;
                ldsm_x4(bh4[bi][0], bh4[bi][1], bh4[bi][2], bh4[bi][3], kb + S_KH + kbr);
            }
            #pragma unroll
            for (int bi = 0; bi < 4; bi++) {
                mma16816(s[2*bi],   qfh[kc][0],qfh[kc][1],qfh[kc][2],qfh[kc][3], bh4[bi][0], bh4[bi][2]);
                mma16816(s[2*bi+1], qfh[kc][0],qfh[kc][1],qfh[kc][2],qfh[kc][3], bh4[bi][1], bh4[bi][3]);
            }
            #pragma unroll
            for (int bi = 0; bi < 4; bi++) {
                unsigned kbr = (unsigned)(bi * 16 + lrow) * 272 + lquad + kc * 32;
                ldsm_x4(bl4[bi][0], bl4[bi][1], bl4[bi][2], bl4[bi][3], kb + S_KL + kbr);
            }
            #pragma unroll
            for (int bi = 0; bi < 4; bi++) {
                mma16816(s[2*bi],   qfh[kc][0],qfh[kc][1],qfh[kc][2],qfh[kc][3], bl4[bi][0], bl4[bi][2]);
                mma16816(s[2*bi+1], qfh[kc][0],qfh[kc][1],qfh[kc][2],qfh[kc][3], bl4[bi][1], bl4[bi][3]);
            }
            ldsm_x4(al[0], al[1], al[2], al[3], aql + kc * 32);
            #pragma unroll
            for (int bi = 0; bi < 4; bi++) {
                mma16816(s[2*bi],   al[0],al[1],al[2],al[3], bh4[bi][0], bh4[bi][2]);
                mma16816(s[2*bi+1], al[0],al[1],al[2],al[3], bh4[bi][1], bh4[bi][3]);
            }
        }

        // ---- softmax numerator: p = exp2(s) (log2e pre-folded), per-lane l ----
        #pragma unroll
        for (int nf = 0; nf < 8; nf++) {
            s[nf][0] = exp2f(s[nf][0]); lacc0 += s[nf][0];
            s[nf][1] = exp2f(s[nf][1]); lacc0 += s[nf][1];
            s[nf][2] = exp2f(s[nf][2]); lacc1 += s[nf][2];
            s[nf][3] = exp2f(s[nf][3]); lacc1 += s[nf][3];
        }

        // ---- P -> bf16 split A-frags (trunc split) ----
        unsigned pah[4][4], pal[4][4];
        #pragma unroll
        for (int kc2 = 0; kc2 < 4; kc2++) {
            #pragma unroll
            for (int r = 0; r < 4; r++) {
                int nf = 2 * kc2 + (r >> 1);
                float v0 = s[nf][(r & 1) * 2], v1 = s[nf][(r & 1) * 2 + 1];
                split2_trunc(v0, v1, pah[kc2][r], pal[kc2][r]);
            }
        }

        // ---- O += P V (fused 3-pass), V-frags double-buffered ----
        #pragma unroll
        for (int kc2 = 0; kc2 < 4; kc2++) {
            unsigned vh4[2][4], vl4[2][4];
            {
                unsigned vr = lrow * 144 + lquad + kc2 * 32;
                ldsm_x4(vh4[0][0], vh4[0][1], vh4[0][2], vh4[0][3], kb + S_VH + vr);
                ldsm_x4(vl4[0][0], vl4[0][1], vl4[0][2], vl4[0][3], kb + S_VL + vr);
            }
            #pragma unroll
            for (int nf2 = 0; nf2 < 8; nf2++) {
                const int cur = nf2 & 1, nxt = cur ^ 1;
                if (nf2 < 7) {
                    unsigned vr = (unsigned)((nf2 + 1) * 16 + lrow) * 144 + lquad + kc2 * 32;
                    ldsm_x4(vh4[nxt][0], vh4[nxt][1], vh4[nxt][2], vh4[nxt][3], kb + S_VH + vr);
                    ldsm_x4(vl4[nxt][0], vl4[nxt][1], vl4[nxt][2], vl4[nxt][3], kb + S_VL + vr);
                }
                mma16816(o[2*nf2],   pah[kc2][0],pah[kc2][1],pah[kc2][2],pah[kc2][3], vh4[cur][0], vh4[cur][2]);
                mma16816(o[2*nf2+1], pah[kc2][0],pah[kc2][1],pah[kc2][2],pah[kc2][3], vh4[cur][1], vh4[cur][3]);
                mma16816(o[2*nf2],   pah[kc2][0],pah[kc2][1],pah[kc2][2],pah[kc2][3], vl4[cur][0], vl4[cur][2]);
                mma16816(o[2*nf2+1], pah[kc2][0],pah[kc2][1],pah[kc2][2],pah[kc2][3], vl4[cur][1], vl4[cur][3]);
                mma16816(o[2*nf2],   pal[kc2][0],pal[kc2][1],pal[kc2][2],pal[kc2][3], vh4[cur][0], vh4[cur][2]);
                mma16816(o[2*nf2+1], pal[kc2][0],pal[kc2][1],pal[kc2][2],pal[kc2][3], vh4[cur][1], vh4[cur][3]);
            }
        }
        __syncthreads();
    }

    // ---- final l reduction across the 4 lanes of each quad ----
    float l0 = lacc0, l1 = lacc1;
    l0 += __shfl_xor_sync(0xffffffffu, l0, 1);
    l0 += __shfl_xor_sync(0xffffffffu, l0, 2);
    l1 += __shfl_xor_sync(0xffffffffu, l1, 1);
    l1 += __shfl_xor_sync(0xffffffffu, l1, 2);

    // ---- epilogue: normalize, split, store to ao [B,S,H] ----
    float il0 = 1.f / l0, il1 = 1.f / l1;
    const int b = bh >> 4, h = bh & 15;
    size_t srow = (size_t)q0 + w * 16 + (lane >> 2);
    size_t base0 = ((size_t)b * Ssz + srow) * Hsz + h * 128 + (lane & 3) * 2;
    size_t base1 = base0 + 8 * (size_t)Hsz;
    #pragma unroll
    for (int nf = 0; nf < 16; nf++) {
        unsigned hw, lw;
        split2_trunc(o[nf][0] * il0, o[nf][1] * il0, hw, lw);
        *(unsigned*)(AOh + base0 + nf * 8) = hw;
        *(unsigned*)(AOl + base0 + nf * 8) = lw;
        split2_trunc(o[nf][2] * il1, o[nf][3] * il1, hw, lw);
        *(unsigned*)(AOh + base1 + nf * 8) = hw;
        *(unsigned*)(AOl + base1 + nf * 8) = lw;
    }
}

// ---------------------------------------------------------------------------
extern "C" void kernel_launch(void* const* d_in, const int* in_sizes, int n_in,
                              void* d_out, int out_size)
{
    const float* x  = (const float*)d_in[0];
    const float* Wq = (const float*)d_in[1];
    const float* bq = (const float*)d_in[2];
    const float* Wk = (const float*)d_in[3];
    const float* bk = (const float*)d_in[4];
    const float* Wv = (const float*)d_in[5];
    const float* bv = (const float*)d_in[6];
    const float* Wo = (const float*)d_in[7];
    const float* bo = (const float*)d_in[8];
    float* out = (float*)d_out;

    __nv_bfloat16 *xhi, *xlo, *whi, *wlo, *qh, *ql, *kh, *kl, *vth, *vtl, *aoh, *aol;
    cudaGetSymbolAddress((void**)&xhi, g_xhi);
    cudaGetSymbolAddress((void**)&xlo, g_xlo);
    cudaGetSymbolAddress((void**)&whi, g_whi);
    cudaGetSymbolAddress((void**)&wlo, g_wlo);
    cudaGetSymbolAddress((void**)&qh,  g_qh);
    cudaGetSymbolAddress((void**)&ql,  g_ql);
    cudaGetSymbolAddress((void**)&kh,  g_kh);
    cudaGetSymbolAddress((void**)&kl,  g_kl);
    cudaGetSymbolAddress((void**)&vth, g_vth);
    cudaGetSymbolAddress((void**)&vtl, g_vtl);
    cudaGetSymbolAddress((void**)&aoh, g_aoh);
    cudaGetSymbolAddress((void**)&aol, g_aol);

    cudaFuncSetAttribute(gemm_qkv, cudaFuncAttributeMaxDynamicSharedMemorySize, GSMEM);
    cudaFuncSetAttribute(gemm_out, cudaFuncAttributeMaxDynamicSharedMemorySize, GSMEM);
    cudaFuncSetAttribute(attn_mma, cudaFuncAttributeMaxDynamicSharedMemorySize, A_SMEM);

    dim3 tgrid(Hsz / 32, Hsz / 32, 4), tblk(32, 8);
    tsplit4_kernel<<<tgrid, tblk>>>(Wq, Wk, Wv, Wo, whi, wlo);
    split_kernel<<<2048, 256>>>(x, xhi, xlo, MK);

    dim3 qkvgrid(Hsz / 64, Msz / 128, 3);    // (32, 64, 3)
    gemm_qkv<<<qkvgrid, 256, GSMEM>>>(xhi, xlo, whi, wlo, bq, bk, bv,
                                      qh, ql, kh, kl, vth, vtl);

    dim3 agrid(Ssz / 128, Bsz * NH);         // (16, 64)
    attn_mma<<<agrid, 256, A_SMEM>>>(qh, ql, kh, kl, vth, vtl, aoh, aol);

    dim3 ogrid(Hsz / 64, Msz / 128);         // (32, 64)
    gemm_out<<<ogrid, 256, GSMEM>>>(aoh, aol, whi + 3 * WK, wlo + 3 * WK, bo, out);
}